// round 7
// baseline (speedup 1.0000x reference)
#include <cuda_runtime.h>

#define N_NODES 100000
#define DIM     128
#define N_EDGES 1600000
#define ALPHA   4

// ---------------- device scratch (static globals; no runtime alloc) ----------------
__device__ int   g_stride;                       // 1 = int32 edge_index, 2 = int64 (low word)
__device__ float g_deg [ALPHA * N_NODES];
__device__ float g_dinv[ALPHA * N_NODES];
__device__ int   g_cnt [ALPHA * N_NODES];
__device__ int   g_offs[ALPHA * (N_NODES + 1)];
__device__ int   g_curs[ALPHA * N_NODES];
__device__ int   g_rows[ALPHA * N_EDGES];        // CSC: source row per edge, grouped by dest
__device__ float g_norm[ALPHA * N_EDGES];        // CSC: norm coefficient per edge
__device__ float g_hw  [(size_t)N_NODES * DIM];  // h @ W^T scratch (51.2 MB, L2-resident)

// ---------------- dtype detection: int64 edge_index has zero high words ----------------
__global__ void detect_kernel(const int* __restrict__ ei32)
{
    if (threadIdx.x == 0 && blockIdx.x == 0) {
        bool all_zero = true;
        #pragma unroll
        for (int i = 1; i < 64; i += 2) all_zero = all_zero && (ei32[i] == 0);
        g_stride = all_zero ? 2 : 1;   // values < 2^31, nonneg: high word 0 iff int64
    }
}

// ---------------- zero deg/cnt ----------------
__global__ void zero_kernel()
{
    int i = blockIdx.x * blockDim.x + threadIdx.x;
    if (i < ALPHA * N_NODES) { g_deg[i] = 0.f; g_cnt[i] = 0; }
}

// ---------------- weighted degree + count histogram over all 4 edge sets ----------------
__global__ void hist_kernel(const int* __restrict__ ei32, const float* __restrict__ ea)
{
    int idx = blockIdx.x * blockDim.x + threadIdx.x;
    if (idx >= ALPHA * N_EDGES) return;
    int l = idx / N_EDGES;
    int e = idx - l * N_EDGES;
    int s = g_stride;
    int col = ei32[(size_t)(l * 2 * N_EDGES + N_EDGES + e) * s];
    if ((unsigned)col >= N_NODES) return;        // safety: never OOB
    float w = ea[(size_t)l * N_EDGES + e];
    atomicAdd(&g_deg[l * N_NODES + col], w);
    atomicAdd(&g_cnt[l * N_NODES + col], 1);
}

// ---------------- dinv = deg > 0 ? rsqrt(deg) : 0 ----------------
__global__ void dinv_kernel()
{
    int i = blockIdx.x * blockDim.x + threadIdx.x;
    if (i >= ALPHA * N_NODES) return;
    float d = g_deg[i];
    g_dinv[i] = (d > 0.f) ? rsqrtf(d) : 0.f;
}

// ---------------- exclusive scan of cnt -> offs (and cursor copy); one block per layer ----------------
__global__ void scan_kernel()
{
    int layer = blockIdx.x;
    const int* c = g_cnt + layer * N_NODES;
    int* o   = g_offs + layer * (N_NODES + 1);
    int* cur = g_curs + layer * N_NODES;

    __shared__ int warp_sums[32];
    __shared__ int s_carry;
    int tid  = threadIdx.x;
    int lane = tid & 31;
    int wid  = tid >> 5;
    if (tid == 0) s_carry = 0;
    __syncthreads();

    for (int base = 0; base < N_NODES; base += 1024) {
        int i = base + tid;
        int v = (i < N_NODES) ? c[i] : 0;
        int x = v;
        #pragma unroll
        for (int d = 1; d < 32; d <<= 1) {
            int t = __shfl_up_sync(0xffffffffu, x, d);
            if (lane >= d) x += t;
        }
        if (lane == 31) warp_sums[wid] = x;
        __syncthreads();
        if (wid == 0) {
            int s = warp_sums[lane];
            #pragma unroll
            for (int d = 1; d < 32; d <<= 1) {
                int t = __shfl_up_sync(0xffffffffu, s, d);
                if (lane >= d) s += t;
            }
            warp_sums[lane] = s;
        }
        __syncthreads();
        int incl = x + ((wid > 0) ? warp_sums[wid - 1] : 0) + s_carry;
        if (i < N_NODES) { o[i] = incl - v; cur[i] = incl - v; }
        __syncthreads();
        if (tid == 1023) s_carry = incl;
        __syncthreads();
    }
    if (tid == 0) o[N_NODES] = s_carry;
}

// ---------------- scatter edges into CSC buckets (atomic cursor, int) ----------------
__global__ void build_kernel(const int* __restrict__ ei32, const float* __restrict__ ea)
{
    int idx = blockIdx.x * blockDim.x + threadIdx.x;
    if (idx >= ALPHA * N_EDGES) return;
    int l = idx / N_EDGES;
    int e = idx - l * N_EDGES;
    int s = g_stride;
    int row = ei32[(size_t)(l * 2 * N_EDGES + e) * s];
    int col = ei32[(size_t)(l * 2 * N_EDGES + N_EDGES + e) * s];
    if ((unsigned)row >= N_NODES || (unsigned)col >= N_NODES) return;  // safety
    float w = ea[(size_t)l * N_EDGES + e];
    float nm = g_dinv[l * N_NODES + row] * w * g_dinv[l * N_NODES + col];
    int pos = atomicAdd(&g_curs[l * N_NODES + col], 1);
    g_rows[(size_t)l * N_EDGES + pos] = row;
    g_norm[(size_t)l * N_EDGES + pos] = nm;
}

// ---------------- GEMM: out[n,d] = sum_k A[n,k] * W[d,k]  (+bias, relu if mode==1) ----------------
// mode 0: write g_hw (no bias/relu). mode 1: write C with bias + relu.
// 64 rows/block, 256 threads: 8 rows/warp, 4 cols/lane. W transposed in smem (pitch 132).
#define GEMM_ROWS 64
#define GEMM_SMEM ((128 * 132 + GEMM_ROWS * 128) * 4)

__global__ void __launch_bounds__(256) gemm_kernel(
    const float* __restrict__ A, const float* __restrict__ W,
    const float* __restrict__ bias, float* __restrict__ C,
    int nrows, int mode)
{
    extern __shared__ float sm[];
    float* Ws = sm;                 // [128][132]  Ws[k*132+d] = W[d][k]
    float* Hs = sm + 128 * 132;     // [64][128]

    int tid  = threadIdx.x;
    int lane = tid & 31;
    int warp = tid >> 5;
    int row0 = blockIdx.x * GEMM_ROWS;

    // load W transposed into smem (coalesced global reads)
    for (int idx = tid; idx < 128 * 128; idx += 256) {
        int d = idx >> 7, k = idx & 127;
        Ws[k * 132 + d] = W[idx];
    }
    // load H tile (float4 coalesced), zero-fill past nrows
    for (int idx = tid; idx < GEMM_ROWS * 32; idx += 256) {
        int r  = idx >> 5;
        int c4 = idx & 31;
        int grow = row0 + r;
        float4 v = make_float4(0.f, 0.f, 0.f, 0.f);
        if (grow < nrows) v = ((const float4*)(A + (size_t)grow * DIM))[c4];
        ((float4*)(Hs + r * DIM))[c4] = v;
    }
    __syncthreads();

    float acc[8][4];
    #pragma unroll
    for (int r = 0; r < 8; r++) { acc[r][0]=0.f; acc[r][1]=0.f; acc[r][2]=0.f; acc[r][3]=0.f; }

    const float* hbase = Hs + (warp * 8) * DIM;
    #pragma unroll 2
    for (int k = 0; k < 128; k++) {
        float4 wv = *(const float4*)&Ws[k * 132 + lane * 4];
        #pragma unroll
        for (int r = 0; r < 8; r++) {
            float hv = hbase[r * DIM + k];
            acc[r][0] = fmaf(hv, wv.x, acc[r][0]);
            acc[r][1] = fmaf(hv, wv.y, acc[r][1]);
            acc[r][2] = fmaf(hv, wv.z, acc[r][2]);
            acc[r][3] = fmaf(hv, wv.w, acc[r][3]);
        }
    }

    float4 bv = make_float4(0.f, 0.f, 0.f, 0.f);
    if (mode == 1) bv = *(const float4*)(bias + lane * 4);

    #pragma unroll
    for (int r = 0; r < 8; r++) {
        int grow = row0 + warp * 8 + r;
        if (grow < nrows) {
            float4 o;
            o.x = acc[r][0]; o.y = acc[r][1]; o.z = acc[r][2]; o.w = acc[r][3];
            float* dst;
            if (mode == 1) {
                o.x = fmaxf(o.x + bv.x, 0.f);
                o.y = fmaxf(o.y + bv.y, 0.f);
                o.z = fmaxf(o.z + bv.z, 0.f);
                o.w = fmaxf(o.w + bv.w, 0.f);
                dst = C;
            } else {
                dst = g_hw;
            }
            *(float4*)(dst + (size_t)grow * DIM + lane * 4) = o;
        }
    }
}

// ---------------- pull aggregation: one warp per destination node, fused bias + relu ----------------
__global__ void __launch_bounds__(256) pull_kernel(
    int layer, const float* __restrict__ bias, float* __restrict__ out)
{
    int node = blockIdx.x * 8 + (threadIdx.x >> 5);
    int lane = threadIdx.x & 31;
    if (node >= N_NODES) return;

    const int*   offs  = g_offs + layer * (N_NODES + 1);
    const int*   rows  = g_rows + (size_t)layer * N_EDGES;
    const float* norms = g_norm + (size_t)layer * N_EDGES;

    int e = offs[node], end = offs[node + 1];
    float4 acc = make_float4(0.f, 0.f, 0.f, 0.f);

    int   r_n  = 0;
    float nm_n = 0.f;
    if (e < end) { r_n = rows[e]; nm_n = norms[e]; }
    for (; e < end; e++) {
        int   r  = r_n;
        float nm = nm_n;
        if (e + 1 < end) { r_n = rows[e + 1]; nm_n = norms[e + 1]; }
        float4 v = *(const float4*)(g_hw + (size_t)r * DIM + lane * 4);
        acc.x = fmaf(nm, v.x, acc.x);
        acc.y = fmaf(nm, v.y, acc.y);
        acc.z = fmaf(nm, v.z, acc.z);
        acc.w = fmaf(nm, v.w, acc.w);
    }

    float4 b = *(const float4*)(bias + lane * 4);
    float4 o;
    o.x = fmaxf(acc.x + b.x, 0.f);
    o.y = fmaxf(acc.y + b.y, 0.f);
    o.z = fmaxf(acc.z + b.z, 0.f);
    o.w = fmaxf(acc.w + b.w, 0.f);
    *(float4*)(out + (size_t)node * DIM + lane * 4) = o;
}

// ---------------- host launch ----------------
extern "C" void kernel_launch(void* const* d_in, const int* in_sizes, int n_in,
                              void* d_out, int out_size)
{
    const float* x      = (const float*)d_in[0];
    const int*   ei32   = (const int*)d_in[1];
    const float* ea     = (const float*)d_in[2];
    const float* lin_w  = (const float*)d_in[3];
    const float* lin_b  = (const float*)d_in[4];
    const float* conv_w = (const float*)d_in[5];
    const float* conv_b = (const float*)d_in[6];
    float*       out    = (float*)d_out;

    // ---- graph preprocessing: dtype detect, degrees, dinv, CSC build (all 4 layers) ----
    {
        int n  = ALPHA * N_NODES;
        int ne = ALPHA * N_EDGES;
        detect_kernel<<<1, 32>>>(ei32);
        zero_kernel<<<(n + 255) / 256, 256>>>();
        hist_kernel<<<(ne + 255) / 256, 256>>>(ei32, ea);
        dinv_kernel<<<(n + 255) / 256, 256>>>();
        scan_kernel<<<ALPHA, 1024>>>();
        build_kernel<<<(ne + 255) / 256, 256>>>(ei32, ea);
    }

    // ---- GEMMs + pull aggregation ----
    cudaFuncSetAttribute(gemm_kernel, cudaFuncAttributeMaxDynamicSharedMemorySize, GEMM_SMEM);
    int gblocks = (N_NODES + GEMM_ROWS - 1) / GEMM_ROWS;
    int pblocks = (N_NODES + 7) / 8;

    // h0 = relu(x @ lin_w^T + lin_b) -> out slab 0
    gemm_kernel<<<gblocks, 256, GEMM_SMEM>>>(x, lin_w, lin_b, out, N_NODES, 1);

    for (int i = 0; i < ALPHA; i++) {
        const float* h_in = out + (size_t)i * N_NODES * DIM;
        float*       h_ot = out + (size_t)(i + 1) * N_NODES * DIM;
        // hw = h_in @ conv_w[i]^T  -> g_hw
        gemm_kernel<<<gblocks, 256, GEMM_SMEM>>>(
            h_in, conv_w + (size_t)i * DIM * DIM, nullptr, nullptr, N_NODES, 0);
        // h_{i+1}[n] = relu( sum_in-edges norm * hw[row] + conv_b[i] )
        pull_kernel<<<pblocks, 256>>>(i, conv_b + (size_t)i * DIM, h_ot);
    }
}

// round 8
// speedup vs baseline: 1.0404x; 1.0404x over previous
#include <cuda_runtime.h>

#define N_NODES 100000
#define DIM     128
#define N_EDGES 1600000
#define ALPHA   4

// ---------------- device scratch (static globals; no runtime alloc) ----------------
__device__ int   g_stride;                       // 1 = int32 edge_index, 2 = int64 (low word)
__device__ float g_deg [ALPHA * N_NODES];
__device__ float g_dinv[ALPHA * N_NODES];
__device__ int   g_cnt [ALPHA * N_NODES];
__device__ int   g_offs[ALPHA * (N_NODES + 1)];
__device__ int   g_curs[ALPHA * N_NODES];
__device__ int2  g_edge[ALPHA * N_EDGES];        // CSC: {src row, norm bits} grouped by dest
__device__ float g_hw  [(size_t)N_NODES * DIM];  // h @ W^T scratch (51.2 MB, L2-resident)

// ---------------- dtype detection: int64 edge_index has zero high words ----------------
__global__ void detect_kernel(const int* __restrict__ ei32)
{
    if (threadIdx.x == 0 && blockIdx.x == 0) {
        bool all_zero = true;
        #pragma unroll
        for (int i = 1; i < 64; i += 2) all_zero = all_zero && (ei32[i] == 0);
        g_stride = all_zero ? 2 : 1;   // values < 2^31, nonneg: high word 0 iff int64
    }
}

// ---------------- zero deg/cnt ----------------
__global__ void zero_kernel()
{
    int i = blockIdx.x * blockDim.x + threadIdx.x;
    if (i < ALPHA * N_NODES) { g_deg[i] = 0.f; g_cnt[i] = 0; }
}

// ---------------- weighted degree + count histogram over all 4 edge sets ----------------
__global__ void hist_kernel(const int* __restrict__ ei32, const float* __restrict__ ea)
{
    int idx = blockIdx.x * blockDim.x + threadIdx.x;
    if (idx >= ALPHA * N_EDGES) return;
    int l = idx / N_EDGES;
    int e = idx - l * N_EDGES;
    int s = g_stride;
    int col = ei32[(size_t)(l * 2 * N_EDGES + N_EDGES + e) * s];
    if ((unsigned)col >= N_NODES) return;        // safety: never OOB
    float w = ea[(size_t)l * N_EDGES + e];
    atomicAdd(&g_deg[l * N_NODES + col], w);
    atomicAdd(&g_cnt[l * N_NODES + col], 1);
}

// ---------------- dinv = deg > 0 ? rsqrt(deg) : 0 ----------------
__global__ void dinv_kernel()
{
    int i = blockIdx.x * blockDim.x + threadIdx.x;
    if (i >= ALPHA * N_NODES) return;
    float d = g_deg[i];
    g_dinv[i] = (d > 0.f) ? rsqrtf(d) : 0.f;
}

// ---------------- exclusive scan of cnt -> offs (and cursor copy); one block per layer ----------------
__global__ void scan_kernel()
{
    int layer = blockIdx.x;
    const int* c = g_cnt + layer * N_NODES;
    int* o   = g_offs + layer * (N_NODES + 1);
    int* cur = g_curs + layer * N_NODES;

    __shared__ int warp_sums[32];
    __shared__ int s_carry;
    int tid  = threadIdx.x;
    int lane = tid & 31;
    int wid  = tid >> 5;
    if (tid == 0) s_carry = 0;
    __syncthreads();

    for (int base = 0; base < N_NODES; base += 1024) {
        int i = base + tid;
        int v = (i < N_NODES) ? c[i] : 0;
        int x = v;
        #pragma unroll
        for (int d = 1; d < 32; d <<= 1) {
            int t = __shfl_up_sync(0xffffffffu, x, d);
            if (lane >= d) x += t;
        }
        if (lane == 31) warp_sums[wid] = x;
        __syncthreads();
        if (wid == 0) {
            int s = warp_sums[lane];
            #pragma unroll
            for (int d = 1; d < 32; d <<= 1) {
                int t = __shfl_up_sync(0xffffffffu, s, d);
                if (lane >= d) s += t;
            }
            warp_sums[lane] = s;
        }
        __syncthreads();
        int incl = x + ((wid > 0) ? warp_sums[wid - 1] : 0) + s_carry;
        if (i < N_NODES) { o[i] = incl - v; cur[i] = incl - v; }
        __syncthreads();
        if (tid == 1023) s_carry = incl;
        __syncthreads();
    }
    if (tid == 0) o[N_NODES] = s_carry;
}

// ---------------- scatter edges into CSC buckets (packed int2 payload) ----------------
__global__ void build_kernel(const int* __restrict__ ei32, const float* __restrict__ ea)
{
    int idx = blockIdx.x * blockDim.x + threadIdx.x;
    if (idx >= ALPHA * N_EDGES) return;
    int l = idx / N_EDGES;
    int e = idx - l * N_EDGES;
    int s = g_stride;
    int row = ei32[(size_t)(l * 2 * N_EDGES + e) * s];
    int col = ei32[(size_t)(l * 2 * N_EDGES + N_EDGES + e) * s];
    if ((unsigned)row >= N_NODES || (unsigned)col >= N_NODES) return;  // safety
    float w = ea[(size_t)l * N_EDGES + e];
    float nm = g_dinv[l * N_NODES + row] * w * g_dinv[l * N_NODES + col];
    int pos = atomicAdd(&g_curs[l * N_NODES + col], 1);
    g_edge[(size_t)l * N_EDGES + pos] = make_int2(row, __float_as_int(nm));
}

// ---------------- GEMM: out[n,d] = sum_k A[n,k] * W[d,k]  (+bias, relu if mode==1) ----------------
// mode 0: write g_hw (no bias/relu). mode 1: write C with bias + relu.
// 64 rows/block, 256 threads: 8 rows/warp, 4 cols/lane. W transposed in smem (pitch 132).
#define GEMM_ROWS 64
#define GEMM_SMEM ((128 * 132 + GEMM_ROWS * 128) * 4)

__global__ void __launch_bounds__(256) gemm_kernel(
    const float* __restrict__ A, const float* __restrict__ W,
    const float* __restrict__ bias, float* __restrict__ C,
    int nrows, int mode)
{
    extern __shared__ float sm[];
    float* Ws = sm;                 // [128][132]  Ws[k*132+d] = W[d][k]
    float* Hs = sm + 128 * 132;     // [64][128]

    int tid  = threadIdx.x;
    int lane = tid & 31;
    int warp = tid >> 5;
    int row0 = blockIdx.x * GEMM_ROWS;

    // load W transposed into smem (coalesced global reads)
    for (int idx = tid; idx < 128 * 128; idx += 256) {
        int d = idx >> 7, k = idx & 127;
        Ws[k * 132 + d] = W[idx];
    }
    // load H tile (float4 coalesced), zero-fill past nrows
    for (int idx = tid; idx < GEMM_ROWS * 32; idx += 256) {
        int r  = idx >> 5;
        int c4 = idx & 31;
        int grow = row0 + r;
        float4 v = make_float4(0.f, 0.f, 0.f, 0.f);
        if (grow < nrows) v = ((const float4*)(A + (size_t)grow * DIM))[c4];
        ((float4*)(Hs + r * DIM))[c4] = v;
    }
    __syncthreads();

    float acc[8][4];
    #pragma unroll
    for (int r = 0; r < 8; r++) { acc[r][0]=0.f; acc[r][1]=0.f; acc[r][2]=0.f; acc[r][3]=0.f; }

    const float* hbase = Hs + (warp * 8) * DIM;
    #pragma unroll 2
    for (int k = 0; k < 128; k++) {
        float4 wv = *(const float4*)&Ws[k * 132 + lane * 4];
        #pragma unroll
        for (int r = 0; r < 8; r++) {
            float hv = hbase[r * DIM + k];
            acc[r][0] = fmaf(hv, wv.x, acc[r][0]);
            acc[r][1] = fmaf(hv, wv.y, acc[r][1]);
            acc[r][2] = fmaf(hv, wv.z, acc[r][2]);
            acc[r][3] = fmaf(hv, wv.w, acc[r][3]);
        }
    }

    float4 bv = make_float4(0.f, 0.f, 0.f, 0.f);
    if (mode == 1) bv = *(const float4*)(bias + lane * 4);

    #pragma unroll
    for (int r = 0; r < 8; r++) {
        int grow = row0 + warp * 8 + r;
        if (grow < nrows) {
            float4 o;
            o.x = acc[r][0]; o.y = acc[r][1]; o.z = acc[r][2]; o.w = acc[r][3];
            float* dst;
            if (mode == 1) {
                o.x = fmaxf(o.x + bv.x, 0.f);
                o.y = fmaxf(o.y + bv.y, 0.f);
                o.z = fmaxf(o.z + bv.z, 0.f);
                o.w = fmaxf(o.w + bv.w, 0.f);
                dst = C;
            } else {
                dst = g_hw;
            }
            *(float4*)(dst + (size_t)grow * DIM + lane * 4) = o;
        }
    }
}

// ---------------- pull aggregation: one warp per destination node, fused bias + relu ----------------
// 2-wide edge unroll with dual accumulators -> 2 outstanding L2 gathers per warp.
__global__ void __launch_bounds__(256) pull_kernel(
    int layer, const float* __restrict__ bias, float* __restrict__ out)
{
    int node = blockIdx.x * 8 + (threadIdx.x >> 5);
    int lane = threadIdx.x & 31;
    if (node >= N_NODES) return;

    const int*  offs  = g_offs + layer * (N_NODES + 1);
    const int2* edges = g_edge + (size_t)layer * N_EDGES;

    int e = offs[node], end = offs[node + 1];
    float4 a0 = make_float4(0.f, 0.f, 0.f, 0.f);
    float4 a1 = make_float4(0.f, 0.f, 0.f, 0.f);

    for (; e + 1 < end; e += 2) {
        int2 p0 = edges[e];
        int2 p1 = edges[e + 1];
        float4 v0 = *(const float4*)(g_hw + (size_t)p0.x * DIM + lane * 4);
        float4 v1 = *(const float4*)(g_hw + (size_t)p1.x * DIM + lane * 4);
        float n0 = __int_as_float(p0.y);
        float n1 = __int_as_float(p1.y);
        a0.x = fmaf(n0, v0.x, a0.x);  a1.x = fmaf(n1, v1.x, a1.x);
        a0.y = fmaf(n0, v0.y, a0.y);  a1.y = fmaf(n1, v1.y, a1.y);
        a0.z = fmaf(n0, v0.z, a0.z);  a1.z = fmaf(n1, v1.z, a1.z);
        a0.w = fmaf(n0, v0.w, a0.w);  a1.w = fmaf(n1, v1.w, a1.w);
    }
    if (e < end) {
        int2 p0 = edges[e];
        float4 v0 = *(const float4*)(g_hw + (size_t)p0.x * DIM + lane * 4);
        float n0 = __int_as_float(p0.y);
        a0.x = fmaf(n0, v0.x, a0.x);
        a0.y = fmaf(n0, v0.y, a0.y);
        a0.z = fmaf(n0, v0.z, a0.z);
        a0.w = fmaf(n0, v0.w, a0.w);
    }

    float4 b = *(const float4*)(bias + lane * 4);
    float4 o;
    o.x = fmaxf(a0.x + a1.x + b.x, 0.f);
    o.y = fmaxf(a0.y + a1.y + b.y, 0.f);
    o.z = fmaxf(a0.z + a1.z + b.z, 0.f);
    o.w = fmaxf(a0.w + a1.w + b.w, 0.f);
    *(float4*)(out + (size_t)node * DIM + lane * 4) = o;
}

// ---------------- host launch ----------------
extern "C" void kernel_launch(void* const* d_in, const int* in_sizes, int n_in,
                              void* d_out, int out_size)
{
    const float* x      = (const float*)d_in[0];
    const int*   ei32   = (const int*)d_in[1];
    const float* ea     = (const float*)d_in[2];
    const float* lin_w  = (const float*)d_in[3];
    const float* lin_b  = (const float*)d_in[4];
    const float* conv_w = (const float*)d_in[5];
    const float* conv_b = (const float*)d_in[6];
    float*       out    = (float*)d_out;

    // One-time host resources (no device memory involved; identical work every call).
    static cudaStream_t s_side = nullptr;
    static cudaEvent_t  ev_fork = nullptr, ev_join = nullptr;
    if (s_side == nullptr) {
        cudaStreamCreateWithFlags(&s_side, cudaStreamNonBlocking);
        cudaEventCreateWithFlags(&ev_fork, cudaEventDisableTiming);
        cudaEventCreateWithFlags(&ev_join, cudaEventDisableTiming);
        cudaFuncSetAttribute(gemm_kernel, cudaFuncAttributeMaxDynamicSharedMemorySize, GEMM_SMEM);
    }

    int gblocks = (N_NODES + GEMM_ROWS - 1) / GEMM_ROWS;
    int pblocks = (N_NODES + 7) / 8;
    int n  = ALPHA * N_NODES;
    int ne = ALPHA * N_EDGES;

    // ---- fork: graph preprocessing on side stream, parallel to first two GEMMs ----
    cudaEventRecord(ev_fork, 0);
    cudaStreamWaitEvent(s_side, ev_fork, 0);

    detect_kernel<<<1, 32, 0, s_side>>>(ei32);
    zero_kernel<<<(n + 255) / 256, 256, 0, s_side>>>();
    hist_kernel<<<(ne + 255) / 256, 256, 0, s_side>>>(ei32, ea);
    dinv_kernel<<<(n + 255) / 256, 256, 0, s_side>>>();
    scan_kernel<<<ALPHA, 1024, 0, s_side>>>();
    build_kernel<<<(ne + 255) / 256, 256, 0, s_side>>>(ei32, ea);
    cudaEventRecord(ev_join, s_side);

    // ---- main stream: h0 = relu(x @ lin_w^T + lin_b), then hw0 = h0 @ conv_w0^T ----
    gemm_kernel<<<gblocks, 256, GEMM_SMEM>>>(x, lin_w, lin_b, out, N_NODES, 1);
    gemm_kernel<<<gblocks, 256, GEMM_SMEM>>>(out, conv_w, nullptr, nullptr, N_NODES, 0);

    // join: pull needs the CSC
    cudaStreamWaitEvent(0, ev_join, 0);

    for (int i = 0; i < ALPHA; i++) {
        float* h_ot = out + (size_t)(i + 1) * N_NODES * DIM;
        // h_{i+1}[n] = relu( sum_in-edges norm * hw[row] + conv_b[i] )
        pull_kernel<<<pblocks, 256>>>(i, conv_b + (size_t)i * DIM, h_ot);
        // hw_{i+1} = h_{i+1} @ conv_w[i+1]^T (skip after last layer)
        if (i + 1 < ALPHA) {
            gemm_kernel<<<gblocks, 256, GEMM_SMEM>>>(
                h_ot, conv_w + (size_t)(i + 1) * DIM * DIM, nullptr, nullptr, N_NODES, 0);
        }
    }
}